// round 2
// baseline (speedup 1.0000x reference)
#include <cuda_runtime.h>
#include <math.h>

// ---------------------------------------------------------------------------
// Problem constants (fixed by the dataset):
//   N=8192 rows, F=1024 input dim, H=2048 hidden, P=128 projection dim
// ---------------------------------------------------------------------------
constexpr int Nrow = 8192;
constexpr int Fdim = 1024;
constexpr int Hdim = 2048;
constexpr int Pdim = 128;
constexpr float INV_T = 10.0f;   // 1 / TEMPERATURE

// Single fused scratch block (no cudaMalloc allowed -> __device__ global).
// Layout (floats):
//   [0,                 Nrow*Hdim)      h1
//   [Nrow*Hdim,         2*Nrow*Hdim)   h2
//   [2*Nrow*Hdim,       +Nrow*Pdim)    z1
//   [...,               +Nrow*Pdim)    z2
//   [...,               +Nrow)         pos
//   [...,               +Nrow)         lse
constexpr size_t OFF_H1  = 0;
constexpr size_t OFF_H2  = OFF_H1 + (size_t)Nrow * Hdim;
constexpr size_t OFF_Z1  = OFF_H2 + (size_t)Nrow * Hdim;
constexpr size_t OFF_Z2  = OFF_Z1 + (size_t)Nrow * Pdim;
constexpr size_t OFF_POS = OFF_Z2 + (size_t)Nrow * Pdim;
constexpr size_t OFF_LSE = OFF_POS + Nrow;
constexpr size_t SCRATCH = OFF_LSE + Nrow;

__device__ float g_scratch[SCRATCH];

// ---------------------------------------------------------------------------
// Tiled SGEMM:  C[M,N] = act(A[M,K] @ B[K,N] + bias[N])
// BM=BN=128, BK=16, 256 threads, 8x8 per-thread microtile, float4 I/O.
// All dims in this problem are exact multiples of the tiles -> no bounds checks.
// ---------------------------------------------------------------------------
constexpr int BM = 128, BN = 128, BK = 16, TM = 8, TN = 8;

template <bool RELU>
__global__ void __launch_bounds__(256, 2)
gemm_bias(const float* __restrict__ A, const float* __restrict__ B,
          const float* __restrict__ bias, float* __restrict__ C,
          int M, int N, int K)
{
    __shared__ float As[BK][BM + 4];   // A tile stored transposed
    __shared__ float Bs[BK][BN + 4];

    const int tid  = threadIdx.x;
    const int trow = tid >> 4;         // 0..15
    const int tcol = tid & 15;         // 0..15

    const float* Ab = A + (size_t)blockIdx.y * BM * K;
    const float* Bb = B + blockIdx.x * BN;

    float acc[TM][TN];
#pragma unroll
    for (int i = 0; i < TM; i++)
#pragma unroll
        for (int j = 0; j < TN; j++) acc[i][j] = 0.f;

    // global->smem load indices (float4 granularity)
    const int aRow = tid >> 2;          // 0..63  (two passes -> 128 rows)
    const int aCol = (tid & 3) << 2;    // 0,4,8,12
    const int bRow = tid >> 5;          // 0..7   (two passes -> 16 rows)
    const int bCol = (tid & 31) << 2;   // 0..124

    for (int kt = 0; kt < K; kt += BK) {
#pragma unroll
        for (int p = 0; p < 2; p++) {
            int r = aRow + p * 64;
            float4 v = *(const float4*)(Ab + (size_t)r * K + kt + aCol);
            As[aCol + 0][r] = v.x; As[aCol + 1][r] = v.y;
            As[aCol + 2][r] = v.z; As[aCol + 3][r] = v.w;
        }
#pragma unroll
        for (int p = 0; p < 2; p++) {
            int r = bRow + p * 8;
            *(float4*)(&Bs[r][bCol]) =
                *(const float4*)(Bb + (size_t)(kt + r) * N + bCol);
        }
        __syncthreads();

#pragma unroll
        for (int k = 0; k < BK; k++) {
            float4 a0 = *(const float4*)(&As[k][trow * TM]);
            float4 a1 = *(const float4*)(&As[k][trow * TM + 4]);
            float4 b0 = *(const float4*)(&Bs[k][tcol * TN]);
            float4 b1 = *(const float4*)(&Bs[k][tcol * TN + 4]);
            float ra[TM] = {a0.x, a0.y, a0.z, a0.w, a1.x, a1.y, a1.z, a1.w};
            float rb[TN] = {b0.x, b0.y, b0.z, b0.w, b1.x, b1.y, b1.z, b1.w};
#pragma unroll
            for (int i = 0; i < TM; i++)
#pragma unroll
                for (int j = 0; j < TN; j++)
                    acc[i][j] = fmaf(ra[i], rb[j], acc[i][j]);
        }
        __syncthreads();
    }

    const int crow0 = blockIdx.y * BM + trow * TM;
    const int ccol0 = blockIdx.x * BN + tcol * TN;
#pragma unroll
    for (int i = 0; i < TM; i++) {
#pragma unroll
        for (int j = 0; j < TN; j += 4) {
            float4 v;
            v.x = acc[i][j + 0] + bias[ccol0 + j + 0];
            v.y = acc[i][j + 1] + bias[ccol0 + j + 1];
            v.z = acc[i][j + 2] + bias[ccol0 + j + 2];
            v.w = acc[i][j + 3] + bias[ccol0 + j + 3];
            if (RELU) {
                v.x = fmaxf(v.x, 0.f); v.y = fmaxf(v.y, 0.f);
                v.z = fmaxf(v.z, 0.f); v.w = fmaxf(v.w, 0.f);
            }
            *(float4*)(C + (size_t)(crow0 + i) * N + ccol0 + j) = v;
        }
    }
}

// ---------------------------------------------------------------------------
// L2 normalize rows in place (P=128 -> one warp per row, float4 per lane)
// Matches F.normalize: x / max(||x||, 1e-12)
// ---------------------------------------------------------------------------
__global__ void norm_rows(float* __restrict__ Z)
{
    int row  = (blockIdx.x * blockDim.x + threadIdx.x) >> 5;
    int lane = threadIdx.x & 31;
    if (row >= Nrow) return;
    float4* p = (float4*)(Z + (size_t)row * Pdim) + lane;
    float4 v = *p;
    float ss = v.x * v.x + v.y * v.y + v.z * v.z + v.w * v.w;
#pragma unroll
    for (int o = 16; o > 0; o >>= 1) ss += __shfl_xor_sync(0xffffffffu, ss, o);
    float d = fmaxf(sqrtf(ss), 1e-12f);
    float inv = 1.0f / d;
    v.x *= inv; v.y *= inv; v.z *= inv; v.w *= inv;
    *p = v;
}

// ---------------------------------------------------------------------------
// pos[i] = (1/T) * dot(r1_i, r2_i) -- one warp per row
// ---------------------------------------------------------------------------
__global__ void pos_kernel(const float* __restrict__ R1,
                           const float* __restrict__ R2,
                           float* __restrict__ pos)
{
    int row  = (blockIdx.x * blockDim.x + threadIdx.x) >> 5;
    int lane = threadIdx.x & 31;
    if (row >= Nrow) return;
    float4 a = *((const float4*)(R1 + (size_t)row * Pdim) + lane);
    float4 b = *((const float4*)(R2 + (size_t)row * Pdim) + lane);
    float s = a.x * b.x + a.y * b.y + a.z * b.z + a.w * b.w;
#pragma unroll
    for (int o = 16; o > 0; o >>= 1) s += __shfl_xor_sync(0xffffffffu, s, o);
    if (lane == 0) pos[row] = INV_T * s;
}

// ---------------------------------------------------------------------------
// Fused logsumexp-GEMM: lse[i] = log( sum_j exp( (1/T) * r1_i . r2_j ) )
// Never materializes the 8192x8192 logits.
// Block = 64 i-rows; r1 slice (64x128) held transposed+padded in SMEM for the
// whole block; r2 streamed in 64x32 K-chunks. 256 threads, 4x4 microtile.
// Dots bounded in [-10,10] -> direct exp-sum, no running max needed.
// Per-row reduction is a fixed-order SMEM sum -> fully deterministic.
// ---------------------------------------------------------------------------
constexpr int LI = 64, LJ = 64;

__global__ void __launch_bounds__(256, 1)
lse_kernel(const float* __restrict__ R1, const float* __restrict__ R2,
           float* __restrict__ lse)
{
    __shared__ float S1[Pdim][LI + 4];   // [k][i]  128x68  (34.8 KB)
    __shared__ float S2[32][LJ + 4];     // [k][j] chunk    ( 8.7 KB)
    __shared__ float red[LI][17];        //                 ( 4.4 KB)

    const int tid = threadIdx.x;
    const int ti  = tid >> 4;            // 0..15 -> i-rows ti*4..ti*4+3
    const int tj  = tid & 15;            // 0..15 -> j-cols tj*4..tj*4+3
    const int i0  = blockIdx.x * LI;

    // Load the block's r1 slice, transposed: S1[k][i]
#pragma unroll
    for (int p = 0; p < 8; p++) {
        int idx = tid + p * 256;
        int row = idx >> 5;              // 0..63
        int c4  = (idx & 31) << 2;       // 0..124
        float4 v = *(const float4*)(R1 + (size_t)(i0 + row) * Pdim + c4);
        S1[c4 + 0][row] = v.x; S1[c4 + 1][row] = v.y;
        S1[c4 + 2][row] = v.z; S1[c4 + 3][row] = v.w;
    }

    float sume[4] = {0.f, 0.f, 0.f, 0.f};

    for (int j0 = 0; j0 < Nrow; j0 += LJ) {
        float acc[4][4];
#pragma unroll
        for (int r = 0; r < 4; r++)
#pragma unroll
            for (int c = 0; c < 4; c++) acc[r][c] = 0.f;

#pragma unroll
        for (int kc = 0; kc < 4; kc++) {
            __syncthreads();             // guard S2 reuse (and S1 load, 1st iter)
#pragma unroll
            for (int p = 0; p < 2; p++) {
                int idx = tid + p * 256;
                int row = idx >> 3;          // 0..63
                int c4  = (idx & 7) << 2;    // 0..28
                float4 v = *(const float4*)(R2 + (size_t)(j0 + row) * Pdim
                                            + kc * 32 + c4);
                S2[c4 + 0][row] = v.x; S2[c4 + 1][row] = v.y;
                S2[c4 + 2][row] = v.z; S2[c4 + 3][row] = v.w;
            }
            __syncthreads();
#pragma unroll
            for (int k = 0; k < 32; k++) {
                float4 a = *(const float4*)(&S1[kc * 32 + k][ti * 4]);
                float4 b = *(const float4*)(&S2[k][tj * 4]);
                float ra[4] = {a.x, a.y, a.z, a.w};
                float rb[4] = {b.x, b.y, b.z, b.w};
#pragma unroll
                for (int r = 0; r < 4; r++)
#pragma unroll
                    for (int c = 0; c < 4; c++)
                        acc[r][c] = fmaf(ra[r], rb[c], acc[r][c]);
            }
        }
        // epilogue: accumulate exp of the 16 finished dots
#pragma unroll
        for (int r = 0; r < 4; r++) {
            sume[r] += __expf(INV_T * acc[r][0]) + __expf(INV_T * acc[r][1])
                     + __expf(INV_T * acc[r][2]) + __expf(INV_T * acc[r][3]);
        }
    }

    __syncthreads();
#pragma unroll
    for (int r = 0; r < 4; r++) red[ti * 4 + r][tj] = sume[r];
    __syncthreads();
    if (tid < LI) {
        float s = 0.f;
#pragma unroll
        for (int t = 0; t < 16; t++) s += red[tid][t];   // fixed order
        lse[i0 + tid] = logf(s);
    }
}

// ---------------------------------------------------------------------------
// Deterministic final reduction: out = mean(lse - pos)
// ---------------------------------------------------------------------------
__global__ void final_reduce(const float* __restrict__ lse,
                             const float* __restrict__ pos,
                             float* __restrict__ out)
{
    __shared__ float s[256];
    float acc = 0.f;
    for (int i = threadIdx.x; i < Nrow; i += 256) acc += lse[i] - pos[i];
    s[threadIdx.x] = acc;
    __syncthreads();
    for (int o = 128; o > 0; o >>= 1) {
        if (threadIdx.x < o) s[threadIdx.x] += s[threadIdx.x + o];
        __syncthreads();
    }
    if (threadIdx.x == 0) out[0] = s[0] / (float)Nrow;
}

// ---------------------------------------------------------------------------
// Launch
// ---------------------------------------------------------------------------
extern "C" void kernel_launch(void* const* d_in, const int* in_sizes, int n_in,
                              void* d_out, int out_size)
{
    const float* f1 = (const float*)d_in[0];
    const float* f2 = (const float*)d_in[1];
    const float* W1 = (const float*)d_in[2];
    const float* b1 = (const float*)d_in[3];
    const float* W2 = (const float*)d_in[4];
    const float* b2 = (const float*)d_in[5];
    const float* W3 = (const float*)d_in[6];
    const float* b3 = (const float*)d_in[7];
    float* out = (float*)d_out;

    float* scratch = nullptr;
    cudaGetSymbolAddress((void**)&scratch, g_scratch);
    float* h1  = scratch + OFF_H1;
    float* h2  = scratch + OFF_H2;
    float* z1  = scratch + OFF_Z1;
    float* z2  = scratch + OFF_Z2;
    float* pos = scratch + OFF_POS;
    float* lse = scratch + OFF_LSE;

    const dim3 blk(256);
    dim3 gl12(Hdim / BN, Nrow / BM);   // (16, 64)
    dim3 gl3 (Pdim / BN, Nrow / BM);   // ( 1, 64)

    // branch 1
    gemm_bias<true ><<<gl12, blk>>>(f1, W1, b1, h1, Nrow, Hdim, Fdim);
    gemm_bias<true ><<<gl12, blk>>>(h1, W2, b2, h2, Nrow, Hdim, Hdim);
    gemm_bias<false><<<gl3,  blk>>>(h2, W3, b3, z1, Nrow, Pdim, Hdim);
    norm_rows<<<Nrow / 8, 256>>>(z1);

    // branch 2 (reuse scratch)
    gemm_bias<true ><<<gl12, blk>>>(f2, W1, b1, h1, Nrow, Hdim, Fdim);
    gemm_bias<true ><<<gl12, blk>>>(h1, W2, b2, h2, Nrow, Hdim, Hdim);
    gemm_bias<false><<<gl3,  blk>>>(h2, W3, b3, z2, Nrow, Pdim, Hdim);
    norm_rows<<<Nrow / 8, 256>>>(z2);

    // contrastive terms
    pos_kernel<<<Nrow / 8, 256>>>(z1, z2, pos);
    lse_kernel<<<Nrow / LI, 256>>>(z1, z2, lse);
    final_reduce<<<1, 256>>>(lse, pos, out);
}

// round 7
// speedup vs baseline: 1.4760x; 1.4760x over previous
#include <cuda_runtime.h>
#include <cuda_bf16.h>
#include <mma.h>
#include <math.h>
#include <stdint.h>

using namespace nvcuda;
typedef __nv_bfloat16 bf16;

// ---------------------------------------------------------------------------
// Problem constants: N=8192 rows, F=1024, H=2048, P=128
// ---------------------------------------------------------------------------
constexpr int Nrow = 8192;
constexpr int Fdim = 1024;
constexpr int Hdim = 2048;
constexpr int Pdim = 128;
constexpr float INV_T = 10.0f;   // 1 / TEMPERATURE

// ---------------------------------------------------------------------------
// Scratch (__device__ globals; no cudaMalloc allowed). Byte offsets.
// ---------------------------------------------------------------------------
constexpr size_t SZ_FEAT_BF  = (size_t)Nrow * Fdim * 2;
constexpr size_t SZ_H_BF     = (size_t)Nrow * Hdim * 2;
constexpr size_t SZ_W1_BF    = (size_t)Fdim * Hdim * 2;
constexpr size_t SZ_W2_BF    = (size_t)Hdim * Hdim * 2;
constexpr size_t SZ_W3_BF    = (size_t)Hdim * Pdim * 2;
constexpr size_t SZ_Z        = (size_t)Nrow * Pdim * 4;

constexpr size_t OFF_F1HI = 0;
constexpr size_t OFF_F1LO = OFF_F1HI + SZ_FEAT_BF;
constexpr size_t OFF_F2HI = OFF_F1LO + SZ_FEAT_BF;
constexpr size_t OFF_F2LO = OFF_F2HI + SZ_FEAT_BF;
constexpr size_t OFF_H1HI = OFF_F2LO + SZ_FEAT_BF;
constexpr size_t OFF_H1LO = OFF_H1HI + SZ_H_BF;
constexpr size_t OFF_H2HI = OFF_H1LO + SZ_H_BF;
constexpr size_t OFF_H2LO = OFF_H2HI + SZ_H_BF;
constexpr size_t OFF_W1HI = OFF_H2LO + SZ_H_BF;
constexpr size_t OFF_W1LO = OFF_W1HI + SZ_W1_BF;
constexpr size_t OFF_W2HI = OFF_W1LO + SZ_W1_BF;
constexpr size_t OFF_W2LO = OFF_W2HI + SZ_W2_BF;
constexpr size_t OFF_W3HI = OFF_W2LO + SZ_W2_BF;
constexpr size_t OFF_W3LO = OFF_W3HI + SZ_W3_BF;
constexpr size_t OFF_Z1   = OFF_W3LO + SZ_W3_BF;
constexpr size_t OFF_Z2   = OFF_Z1 + SZ_Z;
constexpr size_t OFF_POS  = OFF_Z2 + SZ_Z;
constexpr size_t OFF_LSE  = OFF_POS + Nrow * 4;
constexpr size_t SCRATCH_BYTES = OFF_LSE + Nrow * 4;

__device__ __align__(128) unsigned char g_scratch[SCRATCH_BYTES];

// ---------------------------------------------------------------------------
// Prep: fp32 -> bf16 hi/lo split (elementwise)
// ---------------------------------------------------------------------------
__global__ void split_fp32(const float* __restrict__ x,
                           bf16* __restrict__ hi, bf16* __restrict__ lo, int n)
{
    int i = (blockIdx.x * blockDim.x + threadIdx.x) * 4;
    if (i >= n) return;
    float4 v = *(const float4*)(x + i);
    float vv[4] = {v.x, v.y, v.z, v.w};
#pragma unroll
    for (int j = 0; j < 4; j++) {
        bf16 h = __float2bfloat16(vv[j]);
        hi[i + j] = h;
        lo[i + j] = __float2bfloat16(vv[j] - __bfloat162float(h));
    }
}

// ---------------------------------------------------------------------------
// Prep: W[K,N] fp32 -> Wt_hi/Wt_lo [N,K] bf16 (tiled transpose + split)
// ---------------------------------------------------------------------------
__global__ void transpose_split(const float* __restrict__ W,
                                bf16* __restrict__ hi, bf16* __restrict__ lo,
                                int K, int N)
{
    __shared__ float t[32][33];
    int n0 = blockIdx.x * 32, k0 = blockIdx.y * 32;
    int tx = threadIdx.x, ty0 = threadIdx.y;  // block (32, 8)
#pragma unroll
    for (int p = 0; p < 4; p++) {
        int ty = ty0 + p * 8;
        t[ty][tx] = W[(size_t)(k0 + ty) * N + n0 + tx];
    }
    __syncthreads();
#pragma unroll
    for (int p = 0; p < 4; p++) {
        int ty = ty0 + p * 8;
        float v = t[tx][ty];                         // element (k0+tx, n0+ty)
        size_t o = (size_t)(n0 + ty) * K + k0 + tx;  // Wt[n][k]
        bf16 h = __float2bfloat16(v);
        hi[o] = h;
        lo[o] = __float2bfloat16(v - __bfloat162float(h));
    }
}

// ---------------------------------------------------------------------------
// WMMA bf16x3 GEMM:  C[m,n] = act( sum_k A[m,k]*Wt[n,k] + bias[n] )
// Pure nvcuda::wmma (sm_80 baseline ISA): no inline asm, no cp.async,
// static smem only (40960 B < 48 KB, no attribute call needed).
// CTA 128x128, BK=32, 8 warps (4m x 2n), warp tile 32x64 = 2x4 wmma frags.
// Rows padded to 40 bf16 (80 B, multiple of 16 B) -> valid fragment ldm,
// conflict-breaking vs 128B stride.
// Products per k16 step: hi*hi, lo*hi, hi*lo into one fp32 accumulator.
// ---------------------------------------------------------------------------
constexpr int ROWE = 40;   // padded row length in bf16 elements (80 B)

template <bool RELU, bool FP32OUT>
__global__ void __launch_bounds__(256)
gemm_wmma(const bf16* __restrict__ Ahi, const bf16* __restrict__ Alo,
          const bf16* __restrict__ Bhi, const bf16* __restrict__ Blo,
          const float* __restrict__ bias,
          float* __restrict__ Cf,
          bf16* __restrict__ Chi, bf16* __restrict__ Clo,
          int N, int K)
{
    __shared__ __align__(16) bf16 sAhi[128][ROWE];
    __shared__ __align__(16) bf16 sAlo[128][ROWE];
    __shared__ __align__(16) bf16 sBhi[128][ROWE];
    __shared__ __align__(16) bf16 sBlo[128][ROWE];

    const int tid  = threadIdx.x;
    const int wid  = tid >> 5;
    const int lane = tid & 31;
    const int wm   = wid & 3;        // warp m index (0..3) -> m offset wm*32
    const int wn   = wid >> 2;       // warp n index (0..1) -> n offset wn*64
    const int m0   = blockIdx.y * 128;
    const int n0   = blockIdx.x * 128;

    const bf16* gsrc[4] = { Ahi + (size_t)m0 * K, Alo + (size_t)m0 * K,
                            Bhi + (size_t)n0 * K, Blo + (size_t)n0 * K };
    bf16* sdst[4] = { &sAhi[0][0], &sAlo[0][0], &sBhi[0][0], &sBlo[0][0] };

    wmma::fragment<wmma::accumulator, 16, 16, 16, float> acc[2][4];
#pragma unroll
    for (int mf = 0; mf < 2; mf++)
#pragma unroll
        for (int nf = 0; nf < 4; nf++) wmma::fill_fragment(acc[mf][nf], 0.f);

    const int nKb = K / 32;
    for (int kb = 0; kb < nKb; kb++) {
        // ---- fill 4 tiles: 128 rows x 32 bf16 (64B data) each.
        // 2048 16B chunks / 256 threads = 8 per thread.
        const int kbase = kb * 32;
#pragma unroll
        for (int t = 0; t < 8; t++) {
            int c    = tid + t * 256;
            int tile = c >> 9;           // 0..3
            int ix   = c & 511;
            int row  = ix >> 2;          // 0..127
            int ch   = ix & 3;           // 16B chunk within row
            *(uint4*)(sdst[tile] + row * ROWE + ch * 8) =
                *(const uint4*)(gsrc[tile] + (size_t)row * K + kbase + ch * 8);
        }
        __syncthreads();

#pragma unroll
        for (int ks = 0; ks < 2; ks++) {
            wmma::fragment<wmma::matrix_a, 16, 16, 16, bf16, wmma::row_major> fah[2], fal[2];
#pragma unroll
            for (int mf = 0; mf < 2; mf++) {
                wmma::load_matrix_sync(fah[mf], &sAhi[wm * 32 + mf * 16][ks * 16], ROWE);
                wmma::load_matrix_sync(fal[mf], &sAlo[wm * 32 + mf * 16][ks * 16], ROWE);
            }
#pragma unroll
            for (int nf = 0; nf < 4; nf++) {
                // B^T is (k x n) col-major over sB[n][k] with ldm = ROWE
                wmma::fragment<wmma::matrix_b, 16, 16, 16, bf16, wmma::col_major> fbh, fbl;
                wmma::load_matrix_sync(fbh, &sBhi[wn * 64 + nf * 16][ks * 16], ROWE);
                wmma::load_matrix_sync(fbl, &sBlo[wn * 64 + nf * 16][ks * 16], ROWE);
#pragma unroll
                for (int mf = 0; mf < 2; mf++) {
                    wmma::mma_sync(acc[mf][nf], fah[mf], fbh, acc[mf][nf]);  // hi*hi
                    wmma::mma_sync(acc[mf][nf], fal[mf], fbh, acc[mf][nf]);  // lo*hi
                    wmma::mma_sync(acc[mf][nf], fah[mf], fbl, acc[mf][nf]);  // hi*lo
                }
            }
        }
        __syncthreads();   // protect smem before next stage load
    }

    // ---- epilogue: stage each 16x16 fragment through per-warp smem (1KB),
    // apply bias/activation with known (m, n), write out.
    float* staging = (float*)(&sAhi[0][0]) + wid * 256;   // 8 warps x 1KB
    const int r  = lane >> 1;            // 0..15 row within fragment
    const int c0 = (lane & 1) * 8;       // 0 or 8: 8 consecutive cols per lane

#pragma unroll
    for (int mf = 0; mf < 2; mf++) {
#pragma unroll
        for (int nf = 0; nf < 4; nf++) {
            wmma::store_matrix_sync(staging, acc[mf][nf], 16, wmma::mem_row_major);
            __syncwarp();
            const int m  = m0 + wm * 32 + mf * 16 + r;
            const int nb = n0 + wn * 64 + nf * 16 + c0;
            float4 b0 = *(const float4*)(bias + nb);
            float4 b1 = *(const float4*)(bias + nb + 4);
            float v[8];
#pragma unroll
            for (int j = 0; j < 8; j++) v[j] = staging[r * 16 + c0 + j];
            v[0] += b0.x; v[1] += b0.y; v[2] += b0.z; v[3] += b0.w;
            v[4] += b1.x; v[5] += b1.y; v[6] += b1.z; v[7] += b1.w;
            if (RELU) {
#pragma unroll
                for (int j = 0; j < 8; j++) v[j] = fmaxf(v[j], 0.f);
            }
            if (FP32OUT) {
                *(float4*)(Cf + (size_t)m * N + nb)     = make_float4(v[0], v[1], v[2], v[3]);
                *(float4*)(Cf + (size_t)m * N + nb + 4) = make_float4(v[4], v[5], v[6], v[7]);
            } else {
                size_t o = (size_t)m * N + nb;
#pragma unroll
                for (int j = 0; j < 8; j += 2) {
                    bf16 h0 = __float2bfloat16(v[j]);
                    bf16 h1 = __float2bfloat16(v[j + 1]);
                    bf16 l0 = __float2bfloat16(v[j]     - __bfloat162float(h0));
                    bf16 l1 = __float2bfloat16(v[j + 1] - __bfloat162float(h1));
                    *(__nv_bfloat162*)(Chi + o + j) = __nv_bfloat162(h0, h1);
                    *(__nv_bfloat162*)(Clo + o + j) = __nv_bfloat162(l0, l1);
                }
            }
            __syncwarp();   // staging reused by next fragment
        }
    }
}

// ---------------------------------------------------------------------------
// L2 normalize rows in place (P=128 -> one warp per row)
// ---------------------------------------------------------------------------
__global__ void norm_rows(float* __restrict__ Z)
{
    int row  = (blockIdx.x * blockDim.x + threadIdx.x) >> 5;
    int lane = threadIdx.x & 31;
    if (row >= Nrow) return;
    float4* p = (float4*)(Z + (size_t)row * Pdim) + lane;
    float4 v = *p;
    float ss = v.x * v.x + v.y * v.y + v.z * v.z + v.w * v.w;
#pragma unroll
    for (int o = 16; o > 0; o >>= 1) ss += __shfl_xor_sync(0xffffffffu, ss, o);
    float inv = 1.0f / fmaxf(sqrtf(ss), 1e-12f);
    v.x *= inv; v.y *= inv; v.z *= inv; v.w *= inv;
    *p = v;
}

// ---------------------------------------------------------------------------
// pos[i] = (1/T) * dot(r1_i, r2_i)
// ---------------------------------------------------------------------------
__global__ void pos_kernel(const float* __restrict__ R1,
                           const float* __restrict__ R2,
                           float* __restrict__ pos)
{
    int row  = (blockIdx.x * blockDim.x + threadIdx.x) >> 5;
    int lane = threadIdx.x & 31;
    if (row >= Nrow) return;
    float4 a = *((const float4*)(R1 + (size_t)row * Pdim) + lane);
    float4 b = *((const float4*)(R2 + (size_t)row * Pdim) + lane);
    float s = a.x * b.x + a.y * b.y + a.z * b.z + a.w * b.w;
#pragma unroll
    for (int o = 16; o > 0; o >>= 1) s += __shfl_xor_sync(0xffffffffu, s, o);
    if (lane == 0) pos[row] = INV_T * s;
}

// ---------------------------------------------------------------------------
// Fused logsumexp-GEMM (deterministic; never materializes 8192x8192)
// ---------------------------------------------------------------------------
constexpr int LI = 64, LJ = 64;

__global__ void __launch_bounds__(256, 1)
lse_kernel(const float* __restrict__ R1, const float* __restrict__ R2,
           float* __restrict__ lse)
{
    __shared__ float S1[Pdim][LI + 4];
    __shared__ float S2[32][LJ + 4];
    __shared__ float red[LI][17];

    const int tid = threadIdx.x;
    const int ti  = tid >> 4;
    const int tj  = tid & 15;
    const int i0  = blockIdx.x * LI;

#pragma unroll
    for (int p = 0; p < 8; p++) {
        int idx = tid + p * 256;
        int row = idx >> 5;
        int c4  = (idx & 31) << 2;
        float4 v = *(const float4*)(R1 + (size_t)(i0 + row) * Pdim + c4);
        S1[c4 + 0][row] = v.x; S1[c4 + 1][row] = v.y;
        S1[c4 + 2][row] = v.z; S1[c4 + 3][row] = v.w;
    }

    float sume[4] = {0.f, 0.f, 0.f, 0.f};

    for (int j0 = 0; j0 < Nrow; j0 += LJ) {
        float acc[4][4];
#pragma unroll
        for (int r = 0; r < 4; r++)
#pragma unroll
            for (int c = 0; c < 4; c++) acc[r][c] = 0.f;

#pragma unroll
        for (int kc = 0; kc < 4; kc++) {
            __syncthreads();
#pragma unroll
            for (int p = 0; p < 2; p++) {
                int idx = tid + p * 256;
                int row = idx >> 3;
                int c4  = (idx & 7) << 2;
                float4 v = *(const float4*)(R2 + (size_t)(j0 + row) * Pdim
                                            + kc * 32 + c4);
                S2[c4 + 0][row] = v.x; S2[c4 + 1][row] = v.y;
                S2[c4 + 2][row] = v.z; S2[c4 + 3][row] = v.w;
            }
            __syncthreads();
#pragma unroll
            for (int k = 0; k < 32; k++) {
                float4 a = *(const float4*)(&S1[kc * 32 + k][ti * 4]);
                float4 b = *(const float4*)(&S2[k][tj * 4]);
                float ra[4] = {a.x, a.y, a.z, a.w};
                float rb[4] = {b.x, b.y, b.z, b.w};
#pragma unroll
                for (int r = 0; r < 4; r++)
#pragma unroll
                    for (int c = 0; c < 4; c++)
                        acc[r][c] = fmaf(ra[r], rb[c], acc[r][c]);
            }
        }
#pragma unroll
        for (int r = 0; r < 4; r++) {
            sume[r] += __expf(INV_T * acc[r][0]) + __expf(INV_T * acc[r][1])
                     + __expf(INV_T * acc[r][2]) + __expf(INV_T * acc[r][3]);
        }
    }

    __syncthreads();
#pragma unroll
    for (int r = 0; r < 4; r++) red[ti * 4 + r][tj] = sume[r];
    __syncthreads();
    if (tid < LI) {
        float s = 0.f;
#pragma unroll
        for (int t = 0; t < 16; t++) s += red[tid][t];
        lse[i0 + tid] = logf(s);
    }
}

// ---------------------------------------------------------------------------
// Deterministic final reduction: out = mean(lse - pos)
// ---------------------------------------------------------------------------
__global__ void final_reduce(const float* __restrict__ lse,
                             const float* __restrict__ pos,
                             float* __restrict__ out)
{
    __shared__ float s[256];
    float acc = 0.f;
    for (int i = threadIdx.x; i < Nrow; i += 256) acc += lse[i] - pos[i];
    s[threadIdx.x] = acc;
    __syncthreads();
    for (int o = 128; o > 0; o >>= 1) {
        if (threadIdx.x < o) s[threadIdx.x] += s[threadIdx.x + o];
        __syncthreads();
    }
    if (threadIdx.x == 0) out[0] = s[0] / (float)Nrow;
}

// ---------------------------------------------------------------------------
// Launch (no cudaFuncSetAttribute needed: all static smem <= 48 KB)
// ---------------------------------------------------------------------------
extern "C" void kernel_launch(void* const* d_in, const int* in_sizes, int n_in,
                              void* d_out, int out_size)
{
    const float* f1 = (const float*)d_in[0];
    const float* f2 = (const float*)d_in[1];
    const float* W1 = (const float*)d_in[2];
    const float* b1 = (const float*)d_in[3];
    const float* W2 = (const float*)d_in[4];
    const float* b2 = (const float*)d_in[5];
    const float* W3 = (const float*)d_in[6];
    const float* b3 = (const float*)d_in[7];
    float* out = (float*)d_out;

    unsigned char* s = nullptr;
    cudaGetSymbolAddress((void**)&s, g_scratch);
    bf16* f1hi = (bf16*)(s + OFF_F1HI); bf16* f1lo = (bf16*)(s + OFF_F1LO);
    bf16* f2hi = (bf16*)(s + OFF_F2HI); bf16* f2lo = (bf16*)(s + OFF_F2LO);
    bf16* h1hi = (bf16*)(s + OFF_H1HI); bf16* h1lo = (bf16*)(s + OFF_H1LO);
    bf16* h2hi = (bf16*)(s + OFF_H2HI); bf16* h2lo = (bf16*)(s + OFF_H2LO);
    bf16* w1hi = (bf16*)(s + OFF_W1HI); bf16* w1lo = (bf16*)(s + OFF_W1LO);
    bf16* w2hi = (bf16*)(s + OFF_W2HI); bf16* w2lo = (bf16*)(s + OFF_W2LO);
    bf16* w3hi = (bf16*)(s + OFF_W3HI); bf16* w3lo = (bf16*)(s + OFF_W3LO);
    float* z1  = (float*)(s + OFF_Z1);  float* z2  = (float*)(s + OFF_Z2);
    float* pos = (float*)(s + OFF_POS); float* lse = (float*)(s + OFF_LSE);

    // ---- prep: weight transpose+split, feature split ----
    transpose_split<<<dim3(Hdim / 32, Fdim / 32), dim3(32, 8)>>>(W1, w1hi, w1lo, Fdim, Hdim);
    transpose_split<<<dim3(Hdim / 32, Hdim / 32), dim3(32, 8)>>>(W2, w2hi, w2lo, Hdim, Hdim);
    transpose_split<<<dim3(Pdim / 32, Hdim / 32), dim3(32, 8)>>>(W3, w3hi, w3lo, Hdim, Pdim);
    {
        int n = Nrow * Fdim;
        split_fp32<<<n / 4 / 256, 256>>>(f1, f1hi, f1lo, n);
        split_fp32<<<n / 4 / 256, 256>>>(f2, f2hi, f2lo, n);
    }

    const dim3 blk(256);
    const dim3 gHid(Hdim / 128, Nrow / 128);   // (16, 64)
    const dim3 gOut(Pdim / 128, Nrow / 128);   // ( 1, 64)

    // ---- branch 1 ----
    gemm_wmma<true , false><<<gHid, blk>>>(f1hi, f1lo, w1hi, w1lo, b1,
                                           nullptr, h1hi, h1lo, Hdim, Fdim);
    gemm_wmma<true , false><<<gHid, blk>>>(h1hi, h1lo, w2hi, w2lo, b2,
                                           nullptr, h2hi, h2lo, Hdim, Hdim);
    gemm_wmma<false, true ><<<gOut, blk>>>(h2hi, h2lo, w3hi, w3lo, b3,
                                           z1, nullptr, nullptr, Pdim, Hdim);
    norm_rows<<<Nrow / 8, 256>>>(z1);

    // ---- branch 2 (reuse h buffers) ----
    gemm_wmma<true , false><<<gHid, blk>>>(f2hi, f2lo, w1hi, w1lo, b1,
                                           nullptr, h1hi, h1lo, Hdim, Fdim);
    gemm_wmma<true , false><<<gHid, blk>>>(h1hi, h1lo, w2hi, w2lo, b2,
                                           nullptr, h2hi, h2lo, Hdim, Hdim);
    gemm_wmma<false, true ><<<gOut, blk>>>(h2hi, h2lo, w3hi, w3lo, b3,
                                           z2, nullptr, nullptr, Pdim, Hdim);
    norm_rows<<<Nrow / 8, 256>>>(z2);

    // ---- contrastive terms ----
    pos_kernel<<<Nrow / 8, 256>>>(z1, z2, pos);
    lse_kernel<<<Nrow / LI, 256>>>(z1, z2, lse);
    final_reduce<<<1, 256>>>(lse, pos, out);
}

// round 9
// speedup vs baseline: 1.5182x; 1.0286x over previous
#include <cuda_runtime.h>
#include <cuda_bf16.h>
#include <mma.h>
#include <math.h>
#include <stdint.h>

using namespace nvcuda;
typedef __nv_bfloat16 bf16;

// ---------------------------------------------------------------------------
// Problem constants: N=8192 rows, F=1024, H=2048, P=128
// ---------------------------------------------------------------------------
constexpr int Nrow = 8192;
constexpr int Fdim = 1024;
constexpr int Hdim = 2048;
constexpr int Pdim = 128;
constexpr float INV_T = 10.0f;   // 1 / TEMPERATURE

// ---------------------------------------------------------------------------
// Scratch (__device__ globals; no cudaMalloc allowed). Byte offsets.
// ---------------------------------------------------------------------------
constexpr size_t SZ_FEAT_BF  = (size_t)Nrow * Fdim * 2;
constexpr size_t SZ_H_BF     = (size_t)Nrow * Hdim * 2;
constexpr size_t SZ_W1_BF    = (size_t)Fdim * Hdim * 2;
constexpr size_t SZ_W2_BF    = (size_t)Hdim * Hdim * 2;
constexpr size_t SZ_W3_BF    = (size_t)Hdim * Pdim * 2;
constexpr size_t SZ_Z        = (size_t)Nrow * Pdim * 4;

constexpr size_t OFF_F1HI = 0;
constexpr size_t OFF_F1LO = OFF_F1HI + SZ_FEAT_BF;
constexpr size_t OFF_F2HI = OFF_F1LO + SZ_FEAT_BF;
constexpr size_t OFF_F2LO = OFF_F2HI + SZ_FEAT_BF;
constexpr size_t OFF_H1HI = OFF_F2LO + SZ_FEAT_BF;
constexpr size_t OFF_H1LO = OFF_H1HI + SZ_H_BF;
constexpr size_t OFF_H2HI = OFF_H1LO + SZ_H_BF;
constexpr size_t OFF_H2LO = OFF_H2HI + SZ_H_BF;
constexpr size_t OFF_W1HI = OFF_H2LO + SZ_H_BF;
constexpr size_t OFF_W1LO = OFF_W1HI + SZ_W1_BF;
constexpr size_t OFF_W2HI = OFF_W1LO + SZ_W1_BF;
constexpr size_t OFF_W2LO = OFF_W2HI + SZ_W2_BF;
constexpr size_t OFF_W3HI = OFF_W2LO + SZ_W2_BF;
constexpr size_t OFF_W3LO = OFF_W3HI + SZ_W3_BF;
constexpr size_t OFF_Z1   = OFF_W3LO + SZ_W3_BF;
constexpr size_t OFF_Z2   = OFF_Z1 + SZ_Z;
constexpr size_t OFF_POS  = OFF_Z2 + SZ_Z;
constexpr size_t OFF_LSE  = OFF_POS + Nrow * 4;
constexpr size_t SCRATCH_BYTES = OFF_LSE + Nrow * 4;

__device__ __align__(128) unsigned char g_scratch[SCRATCH_BYTES];

// ---------------------------------------------------------------------------
// Prep: fp32 -> bf16 hi/lo split (elementwise)
// ---------------------------------------------------------------------------
__global__ void split_fp32(const float* __restrict__ x,
                           bf16* __restrict__ hi, bf16* __restrict__ lo, int n)
{
    int i = (blockIdx.x * blockDim.x + threadIdx.x) * 4;
    if (i >= n) return;
    float4 v = *(const float4*)(x + i);
    float vv[4] = {v.x, v.y, v.z, v.w};
#pragma unroll
    for (int j = 0; j < 4; j++) {
        bf16 h = __float2bfloat16(vv[j]);
        hi[i + j] = h;
        lo[i + j] = __float2bfloat16(vv[j] - __bfloat162float(h));
    }
}

// ---------------------------------------------------------------------------
// Prep: W[K,N] fp32 -> Wt_hi/Wt_lo [N,K] bf16 (tiled transpose + split)
// ---------------------------------------------------------------------------
__global__ void transpose_split(const float* __restrict__ W,
                                bf16* __restrict__ hi, bf16* __restrict__ lo,
                                int K, int N)
{
    __shared__ float t[32][33];
    int n0 = blockIdx.x * 32, k0 = blockIdx.y * 32;
    int tx = threadIdx.x, ty0 = threadIdx.y;  // block (32, 8)
#pragma unroll
    for (int p = 0; p < 4; p++) {
        int ty = ty0 + p * 8;
        t[ty][tx] = W[(size_t)(k0 + ty) * N + n0 + tx];
    }
    __syncthreads();
#pragma unroll
    for (int p = 0; p < 4; p++) {
        int ty = ty0 + p * 8;
        float v = t[tx][ty];                         // element (k0+tx, n0+ty)
        size_t o = (size_t)(n0 + ty) * K + k0 + tx;  // Wt[n][k]
        bf16 h = __float2bfloat16(v);
        hi[o] = h;
        lo[o] = __float2bfloat16(v - __bfloat162float(h));
    }
}

// ---------------------------------------------------------------------------
// WMMA bf16x3 GEMM with register-prefetch pipeline:
//   C[m,n] = act( sum_k A[m,k]*Wt[n,k] + bias[n] )
// Pure nvcuda::wmma (sm_80 baseline ISA), static smem only (40960 B),
// __launch_bounds__(256) exactly as the passing R7 kernel.
// CTA 128x128, BK=32, 8 warps (4m x 2n), warp tile 32x64 = 2x4 wmma frags.
// Pipeline: next K-block's global loads are issued into registers BEFORE the
// current block's MMA phase, then stored to smem after the trailing sync --
// LDG latency hides behind ~96 HMMA per warp. Addresses are recomputed from
// tid at each use (no persistent pointer arrays -> low register pressure).
// Products per k16 step: hi*hi, lo*hi, hi*lo into one fp32 accumulator.
// ---------------------------------------------------------------------------
constexpr int ROWE = 40;   // padded row length in bf16 elements (80 B)

template <bool RELU, bool FP32OUT>
__global__ void __launch_bounds__(256)
gemm_wmma(const bf16* __restrict__ Ahi, const bf16* __restrict__ Alo,
          const bf16* __restrict__ Bhi, const bf16* __restrict__ Blo,
          const float* __restrict__ bias,
          float* __restrict__ Cf,
          bf16* __restrict__ Chi, bf16* __restrict__ Clo,
          int N, int K)
{
    __shared__ __align__(16) bf16 sAhi[128][ROWE];
    __shared__ __align__(16) bf16 sAlo[128][ROWE];
    __shared__ __align__(16) bf16 sBhi[128][ROWE];
    __shared__ __align__(16) bf16 sBlo[128][ROWE];

    const int tid  = threadIdx.x;
    const int wid  = tid >> 5;
    const int lane = tid & 31;
    const int wm   = wid & 3;        // warp m index (0..3) -> m offset wm*32
    const int wn   = wid >> 2;       // warp n index (0..1) -> n offset wn*64
    const int m0   = blockIdx.y * 128;
    const int n0   = blockIdx.x * 128;

    const bf16* gsrc[4] = { Ahi + (size_t)m0 * K, Alo + (size_t)m0 * K,
                            Bhi + (size_t)n0 * K, Blo + (size_t)n0 * K };
    bf16* sdst[4] = { &sAhi[0][0], &sAlo[0][0], &sBhi[0][0], &sBlo[0][0] };

    wmma::fragment<wmma::accumulator, 16, 16, 16, float> acc[2][4];
#pragma unroll
    for (int mf = 0; mf < 2; mf++)
#pragma unroll
        for (int nf = 0; nf < 4; nf++) wmma::fill_fragment(acc[mf][nf], 0.f);

    const int nKb = K / 32;

    // ---- prologue: prefetch K-block 0 into registers ----
    uint4 pf[8];
#pragma unroll
    for (int t = 0; t < 8; t++) {
        int c    = tid + t * 256;
        int tile = c >> 9;
        int ix   = c & 511;
        int row  = ix >> 2;
        int ch   = ix & 3;
        pf[t] = *(const uint4*)(gsrc[tile] + (size_t)row * K + ch * 8);
    }

    for (int kb = 0; kb < nKb; kb++) {
        // drain prefetch registers into smem
#pragma unroll
        for (int t = 0; t < 8; t++) {
            int c    = tid + t * 256;
            int tile = c >> 9;
            int ix   = c & 511;
            int row  = ix >> 2;
            int ch   = ix & 3;
            *(uint4*)(sdst[tile] + row * ROWE + ch * 8) = pf[t];
        }
        __syncthreads();

        // issue next block's global loads; latency hides behind MMA below
        if (kb + 1 < nKb) {
            const int kbase = (kb + 1) * 32;
#pragma unroll
            for (int t = 0; t < 8; t++) {
                int c    = tid + t * 256;
                int tile = c >> 9;
                int ix   = c & 511;
                int row  = ix >> 2;
                int ch   = ix & 3;
                pf[t] = *(const uint4*)(gsrc[tile] + (size_t)row * K + kbase + ch * 8);
            }
        }

#pragma unroll
        for (int ks = 0; ks < 2; ks++) {
            wmma::fragment<wmma::matrix_a, 16, 16, 16, bf16, wmma::row_major> fah[2], fal[2];
#pragma unroll
            for (int mf = 0; mf < 2; mf++) {
                wmma::load_matrix_sync(fah[mf], &sAhi[wm * 32 + mf * 16][ks * 16], ROWE);
                wmma::load_matrix_sync(fal[mf], &sAlo[wm * 32 + mf * 16][ks * 16], ROWE);
            }
#pragma unroll
            for (int nf = 0; nf < 4; nf++) {
                // B^T is (k x n) col-major over sB[n][k] with ldm = ROWE
                wmma::fragment<wmma::matrix_b, 16, 16, 16, bf16, wmma::col_major> fbh, fbl;
                wmma::load_matrix_sync(fbh, &sBhi[wn * 64 + nf * 16][ks * 16], ROWE);
                wmma::load_matrix_sync(fbl, &sBlo[wn * 64 + nf * 16][ks * 16], ROWE);
#pragma unroll
                for (int mf = 0; mf < 2; mf++) {
                    wmma::mma_sync(acc[mf][nf], fah[mf], fbh, acc[mf][nf]);  // hi*hi
                    wmma::mma_sync(acc[mf][nf], fal[mf], fbh, acc[mf][nf]);  // lo*hi
                    wmma::mma_sync(acc[mf][nf], fah[mf], fbl, acc[mf][nf]);  // hi*lo
                }
            }
        }
        __syncthreads();   // protect smem before next stage store
    }

    // ---- epilogue: stage each 16x16 fragment through per-warp smem (1KB),
    // apply bias/activation with known (m, n), write out.
    float* staging = (float*)(&sAhi[0][0]) + wid * 256;   // 8 warps x 1KB
    const int r  = lane >> 1;            // 0..15 row within fragment
    const int c0 = (lane & 1) * 8;       // 0 or 8: 8 consecutive cols per lane

#pragma unroll
    for (int mf = 0; mf < 2; mf++) {
#pragma unroll
        for (int nf = 0; nf < 4; nf++) {
            wmma::store_matrix_sync(staging, acc[mf][nf], 16, wmma::mem_row_major);
            __syncwarp();
            const int m  = m0 + wm * 32 + mf * 16 + r;
            const int nb = n0 + wn * 64 + nf * 16 + c0;
            float4 b0 = *(const float4*)(bias + nb);
            float4 b1 = *(const float4*)(bias + nb + 4);
            float v[8];
#pragma unroll
            for (int j = 0; j < 8; j++) v[j] = staging[r * 16 + c0 + j];
            v[0] += b0.x; v[1] += b0.y; v[2] += b0.z; v[3] += b0.w;
            v[4] += b1.x; v[5] += b1.y; v[6] += b1.z; v[7] += b1.w;
            if (RELU) {
#pragma unroll
                for (int j = 0; j < 8; j++) v[j] = fmaxf(v[j], 0.f);
            }
            if (FP32OUT) {
                *(float4*)(Cf + (size_t)m * N + nb)     = make_float4(v[0], v[1], v[2], v[3]);
                *(float4*)(Cf + (size_t)m * N + nb + 4) = make_float4(v[4], v[5], v[6], v[7]);
            } else {
                size_t o = (size_t)m * N + nb;
#pragma unroll
                for (int j = 0; j < 8; j += 2) {
                    bf16 h0 = __float2bfloat16(v[j]);
                    bf16 h1 = __float2bfloat16(v[j + 1]);
                    bf16 l0 = __float2bfloat16(v[j]     - __bfloat162float(h0));
                    bf16 l1 = __float2bfloat16(v[j + 1] - __bfloat162float(h1));
                    *(__nv_bfloat162*)(Chi + o + j) = __nv_bfloat162(h0, h1);
                    *(__nv_bfloat162*)(Clo + o + j) = __nv_bfloat162(l0, l1);
                }
            }
            __syncwarp();   // staging reused by next fragment
        }
    }
}

// ---------------------------------------------------------------------------
// L2 normalize rows in place (P=128 -> one warp per row)
// ---------------------------------------------------------------------------
__global__ void norm_rows(float* __restrict__ Z)
{
    int row  = (blockIdx.x * blockDim.x + threadIdx.x) >> 5;
    int lane = threadIdx.x & 31;
    if (row >= Nrow) return;
    float4* p = (float4*)(Z + (size_t)row * Pdim) + lane;
    float4 v = *p;
    float ss = v.x * v.x + v.y * v.y + v.z * v.z + v.w * v.w;
#pragma unroll
    for (int o = 16; o > 0; o >>= 1) ss += __shfl_xor_sync(0xffffffffu, ss, o);
    float inv = 1.0f / fmaxf(sqrtf(ss), 1e-12f);
    v.x *= inv; v.y *= inv; v.z *= inv; v.w *= inv;
    *p = v;
}

// ---------------------------------------------------------------------------
// pos[i] = (1/T) * dot(r1_i, r2_i)
// ---------------------------------------------------------------------------
__global__ void pos_kernel(const float* __restrict__ R1,
                           const float* __restrict__ R2,
                           float* __restrict__ pos)
{
    int row  = (blockIdx.x * blockDim.x + threadIdx.x) >> 5;
    int lane = threadIdx.x & 31;
    if (row >= Nrow) return;
    float4 a = *((const float4*)(R1 + (size_t)row * Pdim) + lane);
    float4 b = *((const float4*)(R2 + (size_t)row * Pdim) + lane);
    float s = a.x * b.x + a.y * b.y + a.z * b.z + a.w * b.w;
#pragma unroll
    for (int o = 16; o > 0; o >>= 1) s += __shfl_xor_sync(0xffffffffu, s, o);
    if (lane == 0) pos[row] = INV_T * s;
}

// ---------------------------------------------------------------------------
// Fused logsumexp-GEMM (deterministic; never materializes 8192x8192)
// ---------------------------------------------------------------------------
constexpr int LI = 64, LJ = 64;

__global__ void __launch_bounds__(256, 1)
lse_kernel(const float* __restrict__ R1, const float* __restrict__ R2,
           float* __restrict__ lse)
{
    __shared__ float S1[Pdim][LI + 4];
    __shared__ float S2[32][LJ + 4];
    __shared__ float red[LI][17];

    const int tid = threadIdx.x;
    const int ti  = tid >> 4;
    const int tj  = tid & 15;
    const int i0  = blockIdx.x * LI;

#pragma unroll
    for (int p = 0; p < 8; p++) {
        int idx = tid + p * 256;
        int row = idx >> 5;
        int c4  = (idx & 31) << 2;
        float4 v = *(const float4*)(R1 + (size_t)(i0 + row) * Pdim + c4);
        S1[c4 + 0][row] = v.x; S1[c4 + 1][row] = v.y;
        S1[c4 + 2][row] = v.z; S1[c4 + 3][row] = v.w;
    }

    float sume[4] = {0.f, 0.f, 0.f, 0.f};

    for (int j0 = 0; j0 < Nrow; j0 += LJ) {
        float acc[4][4];
#pragma unroll
        for (int r = 0; r < 4; r++)
#pragma unroll
            for (int c = 0; c < 4; c++) acc[r][c] = 0.f;

#pragma unroll
        for (int kc = 0; kc < 4; kc++) {
            __syncthreads();
#pragma unroll
            for (int p = 0; p < 2; p++) {
                int idx = tid + p * 256;
                int row = idx >> 3;
                int c4  = (idx & 7) << 2;
                float4 v = *(const float4*)(R2 + (size_t)(j0 + row) * Pdim
                                            + kc * 32 + c4);
                S2[c4 + 0][row] = v.x; S2[c4 + 1][row] = v.y;
                S2[c4 + 2][row] = v.z; S2[c4 + 3][row] = v.w;
            }
            __syncthreads();
#pragma unroll
            for (int k = 0; k < 32; k++) {
                float4 a = *(const float4*)(&S1[kc * 32 + k][ti * 4]);
                float4 b = *(const float4*)(&S2[k][tj * 4]);
                float ra[4] = {a.x, a.y, a.z, a.w};
                float rb[4] = {b.x, b.y, b.z, b.w};
#pragma unroll
                for (int r = 0; r < 4; r++)
#pragma unroll
                    for (int c = 0; c < 4; c++)
                        acc[r][c] = fmaf(ra[r], rb[c], acc[r][c]);
            }
        }
#pragma unroll
        for (int r = 0; r < 4; r++) {
            sume[r] += __expf(INV_T * acc[r][0]) + __expf(INV_T * acc[r][1])
                     + __expf(INV_T * acc[r][2]) + __expf(INV_T * acc[r][3]);
        }
    }

    __syncthreads();
#pragma unroll
    for (int r = 0; r < 4; r++) red[ti * 4 + r][tj] = sume[r];
    __syncthreads();
    if (tid < LI) {
        float s = 0.f;
#pragma unroll
        for (int t = 0; t < 16; t++) s += red[tid][t];
        lse[i0 + tid] = logf(s);
    }
}

// ---------------------------------------------------------------------------
// Deterministic final reduction: out = mean(lse - pos)
// ---------------------------------------------------------------------------
__global__ void final_reduce(const float* __restrict__ lse,
                             const float* __restrict__ pos,
                             float* __restrict__ out)
{
    __shared__ float s[256];
    float acc = 0.f;
    for (int i = threadIdx.x; i < Nrow; i += 256) acc += lse[i] - pos[i];
    s[threadIdx.x] = acc;
    __syncthreads();
    for (int o = 128; o > 0; o >>= 1) {
        if (threadIdx.x < o) s[threadIdx.x] += s[threadIdx.x + o];
        __syncthreads();
    }
    if (threadIdx.x == 0) out[0] = s[0] / (float)Nrow;
}

// ---------------------------------------------------------------------------
// Launch (no cudaFuncSetAttribute needed: all static smem <= 48 KB)
// ---------------------------------------------------------------------------
extern "C" void kernel_launch(void* const* d_in, const int* in_sizes, int n_in,
                              void* d_out, int out_size)
{
    const float* f1 = (const float*)d_in[0];
    const float* f2 = (const float*)d_in[1];
    const float* W1 = (const float*)d_in[2];
    const float* b1 = (const float*)d_in[3];
    const float* W2 = (const float*)d_in[4];
    const float* b2 = (const float*)d_in[5];
    const float* W3 = (const float*)d_in[6];
    const float* b3 = (const float*)d_in[7];
    float* out = (float*)d_out;

    unsigned char* s = nullptr;
    cudaGetSymbolAddress((void**)&s, g_scratch);
    bf16* f1hi = (bf16*)(s + OFF_F1HI); bf16* f1lo = (bf16*)(s + OFF_F1LO);
    bf16* f2hi = (bf16*)(s + OFF_F2HI); bf16* f2lo = (bf16*)(s + OFF_F2LO);
    bf16* h1hi = (bf16*)(s + OFF_H1HI); bf16* h1lo = (bf16*)(s + OFF_H1LO);
    bf16* h2hi = (bf16*)(s + OFF_H2HI); bf16* h2lo = (bf16*)(s + OFF_H2LO);
    bf16* w1hi = (bf16*)(s + OFF_W1HI); bf16* w1lo = (bf16*)(s + OFF_W1LO);
    bf16* w2hi = (bf16*)(s + OFF_W2HI); bf16* w2lo = (bf16*)(s + OFF_W2LO);
    bf16* w3hi = (bf16*)(s + OFF_W3HI); bf16* w3lo = (bf16*)(s + OFF_W3LO);
    float* z1  = (float*)(s + OFF_Z1);  float* z2  = (float*)(s + OFF_Z2);
    float* pos = (float*)(s + OFF_POS); float* lse = (float*)(s + OFF_LSE);

    // ---- prep: weight transpose+split, feature split ----
    transpose_split<<<dim3(Hdim / 32, Fdim / 32), dim3(32, 8)>>>(W1, w1hi, w1lo, Fdim, Hdim);
    transpose_split<<<dim3(Hdim / 32, Hdim / 32), dim3(32, 8)>>>(W2, w2hi, w2lo, Hdim, Hdim);
    transpose_split<<<dim3(Pdim / 32, Hdim / 32), dim3(32, 8)>>>(W3, w3hi, w3lo, Hdim, Pdim);
    {
        int n = Nrow * Fdim;
        split_fp32<<<n / 4 / 256, 256>>>(f1, f1hi, f1lo, n);
        split_fp32<<<n / 4 / 256, 256>>>(f2, f2hi, f2lo, n);
    }

    const dim3 blk(256);
    const dim3 gHid(Hdim / 128, Nrow / 128);   // (16, 64)
    const dim3 gOut(Pdim / 128, Nrow / 128);   // ( 1, 64)

    // ---- branch 1 ----
    gemm_wmma<true , false><<<gHid, blk>>>(f1hi, f1lo, w1hi, w1lo, b1,
                                           nullptr, h1hi, h1lo, Hdim, Fdim);
    gemm_wmma<true , false><<<gHid, blk>>>(h1hi, h1lo, w2hi, w2lo, b2,
                                           nullptr, h2hi, h2lo, Hdim, Hdim);
    gemm_wmma<false, true ><<<gOut, blk>>>(h2hi, h2lo, w3hi, w3lo, b3,
                                           z1, nullptr, nullptr, Pdim, Hdim);
    norm_rows<<<Nrow / 8, 256>>>(z1);

    // ---- branch 2 (reuse h buffers) ----
    gemm_wmma<true , false><<<gHid, blk>>>(f2hi, f2lo, w1hi, w1lo, b1,
                                           nullptr, h1hi, h1lo, Hdim, Fdim);
    gemm_wmma<true , false><<<gHid, blk>>>(h1hi, h1lo, w2hi, w2lo, b2,
                                           nullptr, h2hi, h2lo, Hdim, Hdim);
    gemm_wmma<false, true ><<<gOut, blk>>>(h2hi, h2lo, w3hi, w3lo, b3,
                                           z2, nullptr, nullptr, Pdim, Hdim);
    norm_rows<<<Nrow / 8, 256>>>(z2);

    // ---- contrastive terms ----
    pos_kernel<<<Nrow / 8, 256>>>(z1, z2, pos);
    lse_kernel<<<Nrow / LI, 256>>>(z1, z2, lse);
    final_reduce<<<1, 256>>>(lse, pos, out);
}

// round 11
// speedup vs baseline: 1.6946x; 1.1162x over previous
#include <cuda_runtime.h>
#include <cuda_bf16.h>
#include <mma.h>
#include <math.h>
#include <stdint.h>

using namespace nvcuda;
typedef __nv_bfloat16 bf16;

// ---------------------------------------------------------------------------
// Problem constants: N=8192 rows, F=1024, H=2048, P=128
// ---------------------------------------------------------------------------
constexpr int Nrow = 8192;
constexpr int Fdim = 1024;
constexpr int Hdim = 2048;
constexpr int Pdim = 128;
constexpr float INV_T = 10.0f;   // 1 / TEMPERATURE

// ---------------------------------------------------------------------------
// Scratch (__device__ globals; no cudaMalloc allowed). Byte offsets.
// ---------------------------------------------------------------------------
constexpr size_t SZ_FEAT_BF  = (size_t)Nrow * Fdim * 2;
constexpr size_t SZ_H_BF     = (size_t)Nrow * Hdim * 2;
constexpr size_t SZ_W1_BF    = (size_t)Fdim * Hdim * 2;
constexpr size_t SZ_W2_BF    = (size_t)Hdim * Hdim * 2;
constexpr size_t SZ_W3_BF    = (size_t)Hdim * Pdim * 2;
constexpr size_t SZ_Z        = (size_t)Nrow * Pdim * 4;

constexpr size_t OFF_F1HI = 0;
constexpr size_t OFF_F1LO = OFF_F1HI + SZ_FEAT_BF;
constexpr size_t OFF_F2HI = OFF_F1LO + SZ_FEAT_BF;
constexpr size_t OFF_F2LO = OFF_F2HI + SZ_FEAT_BF;
constexpr size_t OFF_H1HI = OFF_F2LO + SZ_FEAT_BF;
constexpr size_t OFF_H1LO = OFF_H1HI + SZ_H_BF;
constexpr size_t OFF_H2HI = OFF_H1LO + SZ_H_BF;
constexpr size_t OFF_H2LO = OFF_H2HI + SZ_H_BF;
constexpr size_t OFF_W1HI = OFF_H2LO + SZ_H_BF;
constexpr size_t OFF_W1LO = OFF_W1HI + SZ_W1_BF;
constexpr size_t OFF_W2HI = OFF_W1LO + SZ_W1_BF;
constexpr size_t OFF_W2LO = OFF_W2HI + SZ_W2_BF;
constexpr size_t OFF_W3HI = OFF_W2LO + SZ_W2_BF;
constexpr size_t OFF_W3LO = OFF_W3HI + SZ_W3_BF;
constexpr size_t OFF_Z1   = OFF_W3LO + SZ_W3_BF;
constexpr size_t OFF_Z2   = OFF_Z1 + SZ_Z;
constexpr size_t OFF_POS  = OFF_Z2 + SZ_Z;
constexpr size_t OFF_LSE  = OFF_POS + Nrow * 4;
constexpr size_t SCRATCH_BYTES = OFF_LSE + Nrow * 4;

__device__ __align__(128) unsigned char g_scratch[SCRATCH_BYTES];

// ---------------------------------------------------------------------------
// Prep: fp32 -> bf16 hi/lo split (elementwise)
// ---------------------------------------------------------------------------
__global__ void split_fp32(const float* __restrict__ x,
                           bf16* __restrict__ hi, bf16* __restrict__ lo, int n)
{
    int i = (blockIdx.x * blockDim.x + threadIdx.x) * 4;
    if (i >= n) return;
    float4 v = *(const float4*)(x + i);
    float vv[4] = {v.x, v.y, v.z, v.w};
#pragma unroll
    for (int j = 0; j < 4; j++) {
        bf16 h = __float2bfloat16(vv[j]);
        hi[i + j] = h;
        lo[i + j] = __float2bfloat16(vv[j] - __bfloat162float(h));
    }
}

// ---------------------------------------------------------------------------
// Prep: W[K,N] fp32 -> Wt_hi/Wt_lo [N,K] bf16 (tiled transpose + split)
// ---------------------------------------------------------------------------
__global__ void transpose_split(const float* __restrict__ W,
                                bf16* __restrict__ hi, bf16* __restrict__ lo,
                                int K, int N)
{
    __shared__ float t[32][33];
    int n0 = blockIdx.x * 32, k0 = blockIdx.y * 32;
    int tx = threadIdx.x, ty0 = threadIdx.y;  // block (32, 8)
#pragma unroll
    for (int p = 0; p < 4; p++) {
        int ty = ty0 + p * 8;
        t[ty][tx] = W[(size_t)(k0 + ty) * N + n0 + tx];
    }
    __syncthreads();
#pragma unroll
    for (int p = 0; p < 4; p++) {
        int ty = ty0 + p * 8;
        float v = t[tx][ty];                         // element (k0+tx, n0+ty)
        size_t o = (size_t)(n0 + ty) * K + k0 + tx;  // Wt[n][k]
        bf16 h = __float2bfloat16(v);
        hi[o] = h;
        lo[o] = __float2bfloat16(v - __bfloat162float(h));
    }
}

// ---------------------------------------------------------------------------
// WMMA bf16x3 GEMM, 64x64 warp tiles for fragment reuse:
//   C[m,n] = act( sum_k A[m,k]*Wt[n,k] + bias[n] )
// Pure nvcuda::wmma (sm_80 baseline ISA), static smem only (40960 B).
// CTA 128x128, BK=32, 4 warps (2m x 2n), warp tile 64x64 = 4x4 wmma frags.
// LDS-per-HMMA drops ~60% vs the 32x64 tiling: 16 fragment loads per 96
// wmma ops (was 20 per 48). Register budget ~190 (acc 128 + A frags 32 +
// B frags 8 + addressing) -- no spill, 2 CTAs/SM.
// Products per k16 step: hi*hi, lo*hi, hi*lo into one fp32 accumulator.
// ---------------------------------------------------------------------------
constexpr int ROWE = 40;   // padded row length in bf16 elements (80 B)

template <bool RELU, bool FP32OUT>
__global__ void __launch_bounds__(128)
gemm_wmma(const bf16* __restrict__ Ahi, const bf16* __restrict__ Alo,
          const bf16* __restrict__ Bhi, const bf16* __restrict__ Blo,
          const float* __restrict__ bias,
          float* __restrict__ Cf,
          bf16* __restrict__ Chi, bf16* __restrict__ Clo,
          int N, int K)
{
    __shared__ __align__(16) bf16 sAhi[128][ROWE];
    __shared__ __align__(16) bf16 sAlo[128][ROWE];
    __shared__ __align__(16) bf16 sBhi[128][ROWE];
    __shared__ __align__(16) bf16 sBlo[128][ROWE];

    const int tid  = threadIdx.x;
    const int wid  = tid >> 5;
    const int lane = tid & 31;
    const int wm   = wid & 1;        // warp m index (0..1) -> m offset wm*64
    const int wn   = wid >> 1;       // warp n index (0..1) -> n offset wn*64
    const int m0   = blockIdx.y * 128;
    const int n0   = blockIdx.x * 128;

    const bf16* gsrc[4] = { Ahi + (size_t)m0 * K, Alo + (size_t)m0 * K,
                            Bhi + (size_t)n0 * K, Blo + (size_t)n0 * K };
    bf16* sdst[4] = { &sAhi[0][0], &sAlo[0][0], &sBhi[0][0], &sBlo[0][0] };

    wmma::fragment<wmma::accumulator, 16, 16, 16, float> acc[4][4];
#pragma unroll
    for (int mf = 0; mf < 4; mf++)
#pragma unroll
        for (int nf = 0; nf < 4; nf++) wmma::fill_fragment(acc[mf][nf], 0.f);

    const int nKb = K / 32;

    for (int kb = 0; kb < nKb; kb++) {
        // ---- fill 4 tiles: 2048 16B chunks / 128 threads = 16 per thread.
        const int kbase = kb * 32;
#pragma unroll
        for (int t = 0; t < 16; t++) {
            int c    = tid + t * 128;
            int tile = c >> 9;           // 0..3
            int ix   = c & 511;
            int row  = ix >> 2;          // 0..127
            int ch   = ix & 3;           // 16B chunk within row
            *(uint4*)(sdst[tile] + row * ROWE + ch * 8) =
                *(const uint4*)(gsrc[tile] + (size_t)row * K + kbase + ch * 8);
        }
        __syncthreads();

#pragma unroll
        for (int ks = 0; ks < 2; ks++) {
            wmma::fragment<wmma::matrix_a, 16, 16, 16, bf16, wmma::row_major> fah[4], fal[4];
#pragma unroll
            for (int mf = 0; mf < 4; mf++) {
                wmma::load_matrix_sync(fah[mf], &sAhi[wm * 64 + mf * 16][ks * 16], ROWE);
                wmma::load_matrix_sync(fal[mf], &sAlo[wm * 64 + mf * 16][ks * 16], ROWE);
            }
#pragma unroll
            for (int nf = 0; nf < 4; nf++) {
                // B^T is (k x n) col-major over sB[n][k] with ldm = ROWE
                wmma::fragment<wmma::matrix_b, 16, 16, 16, bf16, wmma::col_major> fbh, fbl;
                wmma::load_matrix_sync(fbh, &sBhi[wn * 64 + nf * 16][ks * 16], ROWE);
                wmma::load_matrix_sync(fbl, &sBlo[wn * 64 + nf * 16][ks * 16], ROWE);
#pragma unroll
                for (int mf = 0; mf < 4; mf++) {
                    wmma::mma_sync(acc[mf][nf], fah[mf], fbh, acc[mf][nf]);  // hi*hi
                    wmma::mma_sync(acc[mf][nf], fal[mf], fbh, acc[mf][nf]);  // lo*hi
                    wmma::mma_sync(acc[mf][nf], fah[mf], fbl, acc[mf][nf]);  // hi*lo
                }
            }
        }
        __syncthreads();   // protect smem before next stage load
    }

    // ---- epilogue: stage each 16x16 fragment through per-warp smem (1KB),
    // apply bias/activation with known (m, n), write out.
    float* staging = (float*)(&sAhi[0][0]) + wid * 256;   // 4 warps x 1KB
    const int r  = lane >> 1;            // 0..15 row within fragment
    const int c0 = (lane & 1) * 8;       // 0 or 8: 8 consecutive cols per lane

#pragma unroll
    for (int mf = 0; mf < 4; mf++) {
#pragma unroll
        for (int nf = 0; nf < 4; nf++) {
            wmma::store_matrix_sync(staging, acc[mf][nf], 16, wmma::mem_row_major);
            __syncwarp();
            const int m  = m0 + wm * 64 + mf * 16 + r;
            const int nb = n0 + wn * 64 + nf * 16 + c0;
            float4 b0 = *(const float4*)(bias + nb);
            float4 b1 = *(const float4*)(bias + nb + 4);
            float v[8];
#pragma unroll
            for (int j = 0; j < 8; j++) v[j] = staging[r * 16 + c0 + j];
            v[0] += b0.x; v[1] += b0.y; v[2] += b0.z; v[3] += b0.w;
            v[4] += b1.x; v[5] += b1.y; v[6] += b1.z; v[7] += b1.w;
            if (RELU) {
#pragma unroll
                for (int j = 0; j < 8; j++) v[j] = fmaxf(v[j], 0.f);
            }
            if (FP32OUT) {
                *(float4*)(Cf + (size_t)m * N + nb)     = make_float4(v[0], v[1], v[2], v[3]);
                *(float4*)(Cf + (size_t)m * N + nb + 4) = make_float4(v[4], v[5], v[6], v[7]);
            } else {
                size_t o = (size_t)m * N + nb;
#pragma unroll
                for (int j = 0; j < 8; j += 2) {
                    bf16 h0 = __float2bfloat16(v[j]);
                    bf16 h1 = __float2bfloat16(v[j + 1]);
                    bf16 l0 = __float2bfloat16(v[j]     - __bfloat162float(h0));
                    bf16 l1 = __float2bfloat16(v[j + 1] - __bfloat162float(h1));
                    *(__nv_bfloat162*)(Chi + o + j) = __nv_bfloat162(h0, h1);
                    *(__nv_bfloat162*)(Clo + o + j) = __nv_bfloat162(l0, l1);
                }
            }
            __syncwarp();   // staging reused by next fragment
        }
    }
}

// ---------------------------------------------------------------------------
// L2 normalize rows in place (P=128 -> one warp per row)
// ---------------------------------------------------------------------------
__global__ void norm_rows(float* __restrict__ Z)
{
    int row  = (blockIdx.x * blockDim.x + threadIdx.x) >> 5;
    int lane = threadIdx.x & 31;
    if (row >= Nrow) return;
    float4* p = (float4*)(Z + (size_t)row * Pdim) + lane;
    float4 v = *p;
    float ss = v.x * v.x + v.y * v.y + v.z * v.z + v.w * v.w;
#pragma unroll
    for (int o = 16; o > 0; o >>= 1) ss += __shfl_xor_sync(0xffffffffu, ss, o);
    float inv = 1.0f / fmaxf(sqrtf(ss), 1e-12f);
    v.x *= inv; v.y *= inv; v.z *= inv; v.w *= inv;
    *p = v;
}

// ---------------------------------------------------------------------------
// pos[i] = (1/T) * dot(r1_i, r2_i)
// ---------------------------------------------------------------------------
__global__ void pos_kernel(const float* __restrict__ R1,
                           const float* __restrict__ R2,
                           float* __restrict__ pos)
{
    int row  = (blockIdx.x * blockDim.x + threadIdx.x) >> 5;
    int lane = threadIdx.x & 31;
    if (row >= Nrow) return;
    float4 a = *((const float4*)(R1 + (size_t)row * Pdim) + lane);
    float4 b = *((const float4*)(R2 + (size_t)row * Pdim) + lane);
    float s = a.x * b.x + a.y * b.y + a.z * b.z + a.w * b.w;
#pragma unroll
    for (int o = 16; o > 0; o >>= 1) s += __shfl_xor_sync(0xffffffffu, s, o);
    if (lane == 0) pos[row] = INV_T * s;
}

// ---------------------------------------------------------------------------
// Fused logsumexp-GEMM (deterministic; never materializes 8192x8192)
// ---------------------------------------------------------------------------
constexpr int LI = 64, LJ = 64;

__global__ void __launch_bounds__(256, 1)
lse_kernel(const float* __restrict__ R1, const float* __restrict__ R2,
           float* __restrict__ lse)
{
    __shared__ float S1[Pdim][LI + 4];
    __shared__ float S2[32][LJ + 4];
    __shared__ float red[LI][17];

    const int tid = threadIdx.x;
    const int ti  = tid >> 4;
    const int tj  = tid & 15;
    const int i0  = blockIdx.x * LI;

#pragma unroll
    for (int p = 0; p < 8; p++) {
        int idx = tid + p * 256;
        int row = idx >> 5;
        int c4  = (idx & 31) << 2;
        float4 v = *(const float4*)(R1 + (size_t)(i0 + row) * Pdim + c4);
        S1[c4 + 0][row] = v.x; S1[c4 + 1][row] = v.y;
        S1[c4 + 2][row] = v.z; S1[c4 + 3][row] = v.w;
    }

    float sume[4] = {0.f, 0.f, 0.f, 0.f};

    for (int j0 = 0; j0 < Nrow; j0 += LJ) {
        float acc[4][4];
#pragma unroll
        for (int r = 0; r < 4; r++)
#pragma unroll
            for (int c = 0; c < 4; c++) acc[r][c] = 0.f;

#pragma unroll
        for (int kc = 0; kc < 4; kc++) {
            __syncthreads();
#pragma unroll
            for (int p = 0; p < 2; p++) {
                int idx = tid + p * 256;
                int row = idx >> 3;
                int c4  = (idx & 7) << 2;
                float4 v = *(const float4*)(R2 + (size_t)(j0 + row) * Pdim
                                            + kc * 32 + c4);
                S2[c4 + 0][row] = v.x; S2[c4 + 1][row] = v.y;
                S2[c4 + 2][row] = v.z; S2[c4 + 3][row] = v.w;
            }
            __syncthreads();
#pragma unroll
            for (int k = 0; k < 32; k++) {
                float4 a = *(const float4*)(&S1[kc * 32 + k][ti * 4]);
                float4 b = *(const float4*)(&S2[k][tj * 4]);
                float ra[4] = {a.x, a.y, a.z, a.w};
                float rb[4] = {b.x, b.y, b.z, b.w};
#pragma unroll
                for (int r = 0; r < 4; r++)
#pragma unroll
                    for (int c = 0; c < 4; c++)
                        acc[r][c] = fmaf(ra[r], rb[c], acc[r][c]);
            }
        }
#pragma unroll
        for (int r = 0; r < 4; r++) {
            sume[r] += __expf(INV_T * acc[r][0]) + __expf(INV_T * acc[r][1])
                     + __expf(INV_T * acc[r][2]) + __expf(INV_T * acc[r][3]);
        }
    }

    __syncthreads();
#pragma unroll
    for (int r = 0; r < 4; r++) red[ti * 4 + r][tj] = sume[r];
    __syncthreads();
    if (tid < LI) {
        float s = 0.f;
#pragma unroll
        for (int t = 0; t < 16; t++) s += red[tid][t];
        lse[i0 + tid] = logf(s);
    }
}

// ---------------------------------------------------------------------------
// Deterministic final reduction: out = mean(lse - pos)
// ---------------------------------------------------------------------------
__global__ void final_reduce(const float* __restrict__ lse,
                             const float* __restrict__ pos,
                             float* __restrict__ out)
{
    __shared__ float s[256];
    float acc = 0.f;
    for (int i = threadIdx.x; i < Nrow; i += 256) acc += lse[i] - pos[i];
    s[threadIdx.x] = acc;
    __syncthreads();
    for (int o = 128; o > 0; o >>= 1) {
        if (threadIdx.x < o) s[threadIdx.x] += s[threadIdx.x + o];
        __syncthreads();
    }
    if (threadIdx.x == 0) out[0] = s[0] / (float)Nrow;
}

// ---------------------------------------------------------------------------
// Launch (no cudaFuncSetAttribute needed: all static smem <= 48 KB)
// ---------------------------------------------------------------------------
extern "C" void kernel_launch(void* const* d_in, const int* in_sizes, int n_in,
                              void* d_out, int out_size)
{
    const float* f1 = (const float*)d_in[0];
    const float* f2 = (const float*)d_in[1];
    const float* W1 = (const float*)d_in[2];
    const float* b1 = (const float*)d_in[3];
    const float* W2 = (const float*)d_in[4];
    const float* b2 = (const float*)d_in[5];
    const float* W3 = (const float*)d_in[6];
    const float* b3 = (const float*)d_in[7];
    float* out = (float*)d_out;

    unsigned char* s = nullptr;
    cudaGetSymbolAddress((void**)&s, g_scratch);
    bf16* f1hi = (bf16*)(s + OFF_F1HI); bf16* f1lo = (bf16*)(s + OFF_F1LO);
    bf16* f2hi = (bf16*)(s + OFF_F2HI); bf16* f2lo = (bf16*)(s + OFF_F2LO);
    bf16* h1hi = (bf16*)(s + OFF_H1HI); bf16* h1lo = (bf16*)(s + OFF_H1LO);
    bf16* h2hi = (bf16*)(s + OFF_H2HI); bf16* h2lo = (bf16*)(s + OFF_H2LO);
    bf16* w1hi = (bf16*)(s + OFF_W1HI); bf16* w1lo = (bf16*)(s + OFF_W1LO);
    bf16* w2hi = (bf16*)(s + OFF_W2HI); bf16* w2lo = (bf16*)(s + OFF_W2LO);
    bf16* w3hi = (bf16*)(s + OFF_W3HI); bf16* w3lo = (bf16*)(s + OFF_W3LO);
    float* z1  = (float*)(s + OFF_Z1);  float* z2  = (float*)(s + OFF_Z2);
    float* pos = (float*)(s + OFF_POS); float* lse = (float*)(s + OFF_LSE);

    // ---- prep: weight transpose+split, feature split ----
    transpose_split<<<dim3(Hdim / 32, Fdim / 32), dim3(32, 8)>>>(W1, w1hi, w1lo, Fdim, Hdim);
    transpose_split<<<dim3(Hdim / 32, Hdim / 32), dim3(32, 8)>>>(W2, w2hi, w2lo, Hdim, Hdim);
    transpose_split<<<dim3(Pdim / 32, Hdim / 32), dim3(32, 8)>>>(W3, w3hi, w3lo, Hdim, Pdim);
    {
        int n = Nrow * Fdim;
        split_fp32<<<n / 4 / 256, 256>>>(f1, f1hi, f1lo, n);
        split_fp32<<<n / 4 / 256, 256>>>(f2, f2hi, f2lo, n);
    }

    const dim3 blk(128);
    const dim3 gHid(Hdim / 128, Nrow / 128);   // (16, 64)
    const dim3 gOut(Pdim / 128, Nrow / 128);   // ( 1, 64)

    // ---- branch 1 ----
    gemm_wmma<true , false><<<gHid, blk>>>(f1hi, f1lo, w1hi, w1lo, b1,
                                           nullptr, h1hi, h1lo, Hdim, Fdim);
    gemm_wmma<true , false><<<gHid, blk>>>(h1hi, h1lo, w2hi, w2lo, b2,
                                           nullptr, h2hi, h2lo, Hdim, Hdim);
    gemm_wmma<false, true ><<<gOut, blk>>>(h2hi, h2lo, w3hi, w3lo, b3,
                                           z1, nullptr, nullptr, Pdim, Hdim);
    norm_rows<<<Nrow / 8, 256>>>(z1);

    // ---- branch 2 (reuse h buffers) ----
    gemm_wmma<true , false><<<gHid, blk>>>(f2hi, f2lo, w1hi, w1lo, b1,
                                           nullptr, h1hi, h1lo, Hdim, Fdim);
    gemm_wmma<true , false><<<gHid, blk>>>(h1hi, h1lo, w2hi, w2lo, b2,
                                           nullptr, h2hi, h2lo, Hdim, Hdim);
    gemm_wmma<false, true ><<<gOut, blk>>>(h2hi, h2lo, w3hi, w3lo, b3,
                                           z2, nullptr, nullptr, Pdim, Hdim);
    norm_rows<<<Nrow / 8, 256>>>(z2);

    // ---- contrastive terms ----
    pos_kernel<<<Nrow / 8, 256>>>(z1, z2, pos);
    lse_kernel<<<Nrow / LI, 256>>>(z1, z2, lse);
    final_reduce<<<1, 256>>>(lse, pos, out);
}